// round 5
// baseline (speedup 1.0000x reference)
#include <cuda_runtime.h>
#include <math.h>

// Problem constants
#define BB   32
#define LL   2048
#define DIN  64
#define NC   32
#define DC   16
#define OUTD 512           // NC*DC
#define EPSQ 1e-7f

#define K1_CHUNKS 16
#define K3_CHUNKS 32       // blocks per batch in routing pass (64 l's each)
#define K3_WARPS  4
#define K3_LPW    16       // l's per warp

typedef unsigned long long ull;

// Scratch (static device allocations only — no cudaMalloc allowed)
__device__ float g_colsum_part[BB][K1_CHUNKS][DIN];
__device__ float g_s_part[BB][K3_CHUNKS][NC][DIN];   // 8 MB
__device__ float g_v[BB][NC][DIN];

// ---- f32x2 packed helpers (ptxas won't auto-fuse; PTX-only path) ----------
union F4U { float4 f4; ull u2[2]; };

__device__ __forceinline__ ull fma2(ull a, ull b, ull c) {
    ull d;
    asm("fma.rn.f32x2 %0, %1, %2, %3;" : "=l"(d) : "l"(a), "l"(b), "l"(c));
    return d;
}
__device__ __forceinline__ ull pack2(float lo, float hi) {
    ull r;
    asm("mov.b64 %0, {%1, %2};" : "=l"(r) : "f"(lo), "f"(hi));
    return r;
}
__device__ __forceinline__ float2 unpack2(ull p) {
    float2 r;
    asm("mov.b64 {%0, %1}, %2;" : "=f"(r.x), "=f"(r.y) : "l"(p));
    return r;
}

// ---------------------------------------------------------------------------
// K1: column sums  colsum_part[b][chunk][i] = sum over 128 l's of u[b,l,i]
// grid (K1_CHUNKS, BB), 256 threads
// ---------------------------------------------------------------------------
__global__ void k1_colsum(const float* __restrict__ u) {
    const int b = blockIdx.y, chunk = blockIdx.x;
    const int tid = threadIdx.x;
    const int col4 = tid & 15;
    const int g    = tid >> 4;

    const float4* up = (const float4*)(u + ((size_t)b * LL + (size_t)chunk * 128) * DIN);
    float4 acc = make_float4(0.f, 0.f, 0.f, 0.f);
    #pragma unroll
    for (int r = 0; r < 8; r++) {
        float4 x = up[(size_t)(g + r * 16) * 16 + col4];
        acc.x += x.x; acc.y += x.y; acc.z += x.z; acc.w += x.w;
    }
    __shared__ float4 red[16][16];
    red[g][col4] = acc;
    __syncthreads();
    if (tid < 16) {
        float4 s = red[0][tid];
        #pragma unroll
        for (int i = 1; i < 16; i++) {
            float4 x = red[i][tid];
            s.x += x.x; s.y += x.y; s.z += x.z; s.w += x.w;
        }
        ((float4*)g_colsum_part[b][chunk])[tid] = s;
    }
}

// ---------------------------------------------------------------------------
// K2: per-(b,n) epilogue, 128 threads (4 warps) per block for 4x MLP in
// the partial-sum sweep. grid (NC, BB).
//   phase 1: 4 warp-groups each sum 8 chunks -> smem tree combine (deterministic)
//   phase 2: warp 0: raw[d] = s.W column dot; squash; out
//   phase 3 (mode 0/1): threads 0..63 compute v[n][i] -> g_v
// ---------------------------------------------------------------------------
__global__ void __launch_bounds__(128, 8) k2_update(const float* __restrict__ W,
                                                    float* __restrict__ out_final,
                                                    int mode) {
    const int n = blockIdx.x, b = blockIdx.y;
    const int t = threadIdx.x;
    const int lane = t & 31;
    const int grp  = t >> 5;          // 0..3

    __shared__ float red[4][DIN];
    __shared__ float s_sm[DIN];
    __shared__ float out_sm[DC];

    if (mode == 0) {
        if (grp == 0) {
            float a0 = 0.f, a1 = 0.f;
            #pragma unroll
            for (int c = 0; c < K1_CHUNKS; c++) {
                a0 += g_colsum_part[b][c][lane];
                a1 += g_colsum_part[b][c][lane + 32];
            }
            s_sm[lane]      = a0 * (1.0f / 32.0f);
            s_sm[lane + 32] = a1 * (1.0f / 32.0f);
        }
        __syncthreads();
    } else {
        float a0 = 0.f, a1 = 0.f;
        #pragma unroll
        for (int cc = 0; cc < K3_CHUNKS / 4; cc++) {
            const int c = grp + cc * 4;
            const float* base = &g_s_part[b][c][n][0];
            a0 += base[lane];
            a1 += base[lane + 32];
        }
        red[grp][lane]      = a0;
        red[grp][lane + 32] = a1;
        __syncthreads();
        if (grp == 0) {
            s_sm[lane]      = red[0][lane] + red[1][lane] + red[2][lane] + red[3][lane];
            s_sm[lane + 32] = red[0][lane + 32] + red[1][lane + 32]
                            + red[2][lane + 32] + red[3][lane + 32];
        }
        __syncthreads();
    }

    // phase 2: warp 0 computes raw + squash
    if (grp == 0) {
        float raw = 0.f;
        if (lane < DC) {
            const float* Wc = W + (size_t)n * DC + lane;   // W[i*512 + n*16 + lane]
            #pragma unroll
            for (int i = 0; i < DIN; i++)
                raw = fmaf(s_sm[i], Wc[(size_t)i * OUTD], raw);
        }
        float s2 = raw * raw;
        #pragma unroll
        for (int off = 8; off; off >>= 1)
            s2 += __shfl_xor_sync(0xffffffffu, s2, off, 16);
        float o = raw * rsqrtf(s2 + EPSQ);
        if (lane < DC) {
            if (mode == 2) out_final[(size_t)b * OUTD + (size_t)n * DC + lane] = o;
            else           out_sm[lane] = o;
        }
    }

    if (mode != 2) {
        __syncthreads();
        // phase 3: threads 0..63 compute v[n][i]
        if (t < DIN) {
            const float* Wr = W + (size_t)t * OUTD + (size_t)n * DC;
            float v = 0.f;
            #pragma unroll
            for (int d = 0; d < DC; d++)
                v = fmaf(Wr[d], out_sm[d], v);
            g_v[b][n][t] = v;
        }
    }
}

// ---------------------------------------------------------------------------
// K3: fused routing pass, f32x2-packed FMAs, 2 l's per iteration.
// Per (b,l): logits[n] = u[l,:]·v[n,:]; c = softmax over n; s[n,:] += c*u[l,:]
// Lane n owns v[n] and s[n] as 32 packed f32x2 registers each.
// No max-subtract in softmax: |logit| << 88, exp safe.
// grid (K3_CHUNKS, BB), 128 threads (4 warps).
// ---------------------------------------------------------------------------
__global__ void __launch_bounds__(128, 3) k3_route(const float* __restrict__ u) {
    const int b = blockIdx.y, chunk = blockIdx.x;
    const int w = threadIdx.x >> 5;
    const int lane = threadIdx.x & 31;       // lane == capsule index n

    __shared__ float u_buf[K3_WARPS][2][64];
    __shared__ float s_blk[K3_WARPS][NC][65];   // padded: conflict-free stores

    // v[b][lane][:] as 32 f32x2 packs (free punning off float4 loads)
    ull v2[32];
    {
        const float4* vp = (const float4*)(&g_v[b][lane][0]);
        #pragma unroll
        for (int k = 0; k < 16; k++) {
            F4U t; t.f4 = vp[k];
            v2[2 * k]     = t.u2[0];
            v2[2 * k + 1] = t.u2[1];
        }
    }

    ull s2[32];
    #pragma unroll
    for (int k = 0; k < 32; k++) s2[k] = 0ull;   // bits of (0.f, 0.f)

    const int l0 = chunk * (K3_WARPS * K3_LPW) + w * K3_LPW;
    const float* ub = u + ((size_t)b * LL + l0) * DIN;

    for (int j = 0; j < K3_LPW; j += 2) {
        // cooperative row loads: 2 rows of 64 floats, one float2 per lane each
        float2 ra = ((const float2*)(ub + (size_t)j * DIN))[lane];
        float2 rb = ((const float2*)(ub + (size_t)(j + 1) * DIN))[lane];
        __syncwarp();                         // WAR vs previous iteration's reads
        ((float2*)u_buf[w][0])[lane] = ra;
        ((float2*)u_buf[w][1])[lane] = rb;
        __syncwarp();
        const float4* uA4 = (const float4*)u_buf[w][0];
        const float4* uB4 = (const float4*)u_buf[w][1];

        // packed logit dots: 2 accumulator packs per row
        ull a0 = 0ull, a1 = 0ull, b0 = 0ull, b1 = 0ull;
        #pragma unroll
        for (int k = 0; k < 16; k++) {
            F4U xA; xA.f4 = uA4[k];
            F4U xB; xB.f4 = uB4[k];
            a0 = fma2(xA.u2[0], v2[2 * k],     a0);
            a1 = fma2(xA.u2[1], v2[2 * k + 1], a1);
            b0 = fma2(xB.u2[0], v2[2 * k],     b0);
            b1 = fma2(xB.u2[1], v2[2 * k + 1], b1);
        }
        float2 fa0 = unpack2(a0), fa1 = unpack2(a1);
        float2 fb0 = unpack2(b0), fb1 = unpack2(b1);
        float eA = __expf((fa0.x + fa0.y) + (fa1.x + fa1.y));
        float eB = __expf((fb0.x + fb0.y) + (fb1.x + fb1.y));
        float sA = eA, sB = eB;
        #pragma unroll
        for (int off = 16; off; off >>= 1) {
            sA += __shfl_xor_sync(0xffffffffu, sA, off);
            sB += __shfl_xor_sync(0xffffffffu, sB, off);
        }
        ull cpA = pack2(__fdividef(eA, sA), __fdividef(eA, sA));
        ull cpB = pack2(__fdividef(eB, sB), __fdividef(eB, sB));

        // packed accumulate: s += cA*uA + cB*uB
        #pragma unroll
        for (int k = 0; k < 16; k++) {
            F4U xA; xA.f4 = uA4[k];
            F4U xB; xB.f4 = uB4[k];
            s2[2 * k]     = fma2(cpA, xA.u2[0], fma2(cpB, xB.u2[0], s2[2 * k]));
            s2[2 * k + 1] = fma2(cpA, xA.u2[1], fma2(cpB, xB.u2[1], s2[2 * k + 1]));
        }
    }

    // dump register s into padded smem (stride 65 -> conflict-free)
    #pragma unroll
    for (int k = 0; k < 32; k++) {
        float2 t = unpack2(s2[k]);
        s_blk[w][lane][2 * k]     = t.x;
        s_blk[w][lane][2 * k + 1] = t.y;
    }
    __syncthreads();

    // cross-warp reduce, deterministic, coalesced write of this block's partial
    float* outp = (float*)g_s_part[b][chunk];
    for (int e = threadIdx.x; e < NC * DIN; e += 128) {
        int n = e >> 6, i = e & 63;
        outp[e] = s_blk[0][n][i] + s_blk[1][n][i] + s_blk[2][n][i] + s_blk[3][n][i];
    }
}

// ---------------------------------------------------------------------------
extern "C" void kernel_launch(void* const* d_in, const int* in_sizes, int n_in,
                              void* d_out, int out_size) {
    const float* u = (const float*)d_in[0];   // [32, 2048, 64]
    const float* W = (const float*)d_in[1];   // [1, 64, 512]
    float* out = (float*)d_out;               // [32, 32, 16]

    // iteration 0: uniform c -> colsum path
    k1_colsum<<<dim3(K1_CHUNKS, BB), 256>>>(u);
    k2_update<<<dim3(NC, BB), 128>>>(W, out, 0);   // outputs0 + v0
    // iteration 1
    k3_route<<<dim3(K3_CHUNKS, BB), 128>>>(u);
    k2_update<<<dim3(NC, BB), 128>>>(W, out, 1);   // outputs1 + v1
    // iteration 2 (final)
    k3_route<<<dim3(K3_CHUNKS, BB), 128>>>(u);
    k2_update<<<dim3(NC, BB), 128>>>(W, out, 2);   // outputs2 -> d_out
}

// round 7
// speedup vs baseline: 1.7920x; 1.7920x over previous
#include <cuda_runtime.h>
#include <math.h>

// Problem constants
#define BB   32
#define LL   2048
#define DIN  64
#define NC   32
#define DC   16
#define OUTD 512           // NC*DC
#define EPSQ 1e-7f

#define K1_CHUNKS 16
#define K3_CHUNKS 8        // blocks per batch in routing pass (256 l's each)
#define K3_WARPS  4
#define K3_LPW    64       // l's per warp

// Scratch (static device allocations only — no cudaMalloc allowed)
__device__ float g_colsum_part[BB][K1_CHUNKS][DIN];
__device__ float g_s_part[BB][K3_CHUNKS][NC][DIN];   // 2 MB
__device__ float g_v[BB][NC][DIN];

// ---------------------------------------------------------------------------
// K1: column sums  colsum_part[b][chunk][i] = sum over 128 l's of u[b,l,i]
// grid (K1_CHUNKS, BB), 256 threads
// ---------------------------------------------------------------------------
__global__ void k1_colsum(const float* __restrict__ u) {
    const int b = blockIdx.y, chunk = blockIdx.x;
    const int tid = threadIdx.x;
    const int col4 = tid & 15;
    const int g    = tid >> 4;

    const float4* up = (const float4*)(u + ((size_t)b * LL + (size_t)chunk * 128) * DIN);
    float4 acc = make_float4(0.f, 0.f, 0.f, 0.f);
    #pragma unroll
    for (int r = 0; r < 8; r++) {
        float4 x = up[(size_t)(g + r * 16) * 16 + col4];
        acc.x += x.x; acc.y += x.y; acc.z += x.z; acc.w += x.w;
    }
    __shared__ float4 red[16][16];
    red[g][col4] = acc;
    __syncthreads();
    if (tid < 16) {
        float4 s = red[0][tid];
        #pragma unroll
        for (int i = 1; i < 16; i++) {
            float4 x = red[i][tid];
            s.x += x.x; s.y += x.y; s.z += x.z; s.w += x.w;
        }
        ((float4*)g_colsum_part[b][chunk])[tid] = s;
    }
}

// ---------------------------------------------------------------------------
// K2: per-(b,n) epilogue. grid (NC, BB), 64 threads.
//   phase 1: thread t sums chunk partials for element i=t (MLP 8, coalesced)
//   phase 2: warp 0 (lanes<16): raw[d] = s.W column dot; squash
//   phase 3 (mode 0/1): all 64 threads compute v[n][i] -> g_v
// ---------------------------------------------------------------------------
__global__ void __launch_bounds__(64, 16) k2_update(const float* __restrict__ W,
                                                    float* __restrict__ out_final,
                                                    int mode) {
    const int n = blockIdx.x, b = blockIdx.y;
    const int t = threadIdx.x;        // 0..63 == element index i

    __shared__ float s_sm[DIN];
    __shared__ float out_sm[DC];

    float a = 0.f;
    if (mode == 0) {
        #pragma unroll
        for (int c = 0; c < K1_CHUNKS; c++)
            a += g_colsum_part[b][c][t];
        a *= (1.0f / 32.0f);
    } else {
        #pragma unroll
        for (int c = 0; c < K3_CHUNKS; c++)
            a += g_s_part[b][c][n][t];
    }
    s_sm[t] = a;
    __syncthreads();

    // phase 2: warp 0 computes raw + squash
    if (t < 32) {
        float raw = 0.f;
        if (t < DC) {
            const float* Wc = W + (size_t)n * DC + t;   // W[i*512 + n*16 + t]
            #pragma unroll
            for (int i = 0; i < DIN; i++)
                raw = fmaf(s_sm[i], Wc[(size_t)i * OUTD], raw);
        }
        float s2 = raw * raw;
        #pragma unroll
        for (int off = 8; off; off >>= 1)
            s2 += __shfl_xor_sync(0xffffffffu, s2, off, 16);
        float o = raw * rsqrtf(s2 + EPSQ);
        if (t < DC) {
            if (mode == 2) out_final[(size_t)b * OUTD + (size_t)n * DC + t] = o;
            else           out_sm[t] = o;
        }
    }

    if (mode != 2) {
        __syncthreads();
        // phase 3: all 64 threads compute v[n][i], i = t
        const float* Wr = W + (size_t)t * OUTD + (size_t)n * DC;
        float v = 0.f;
        #pragma unroll
        for (int d = 0; d < DC; d++)
            v = fmaf(Wr[d], out_sm[d], v);
        g_v[b][n][t] = v;
    }
}

// ---------------------------------------------------------------------------
// K3: fused routing pass (scalar, proven form), 2 l's per iteration.
// Per (b,l): logits[n] = u[l,:]·v[n,:]; c = softmax over n; s[n,:] += c*u[l,:]
// Warp = 64 l's; lane n owns v[n] and s[n] in registers.
// No max-subtract in softmax: |logit| << 88, exp safe.
// grid (K3_CHUNKS, BB), 128 threads (4 warps).
// ---------------------------------------------------------------------------
__global__ void __launch_bounds__(128, 1) k3_route(const float* __restrict__ u) {
    const int b = blockIdx.y, chunk = blockIdx.x;
    const int w = threadIdx.x >> 5;
    const int lane = threadIdx.x & 31;       // lane == capsule index n

    __shared__ float u_buf[K3_WARPS][2][64];
    __shared__ float s_blk[K3_WARPS][NC][65];   // padded: conflict-free stores

    // Load v[b][lane][:] into registers (once per 64 l's now)
    float4 v4[16];
    const float4* vp = (const float4*)(&g_v[b][lane][0]);
    #pragma unroll
    for (int k = 0; k < 16; k++) v4[k] = vp[k];

    float4 s4[16];
    #pragma unroll
    for (int k = 0; k < 16; k++) s4[k] = make_float4(0.f, 0.f, 0.f, 0.f);

    const int l0 = chunk * (K3_WARPS * K3_LPW) + w * K3_LPW;
    const float* ub = u + ((size_t)b * LL + l0) * DIN;

    for (int j = 0; j < K3_LPW; j += 2) {
        // cooperative row loads: 2 rows of 64 floats, one float2 per lane each
        float2 ra = ((const float2*)(ub + (size_t)j * DIN))[lane];
        float2 rb = ((const float2*)(ub + (size_t)(j + 1) * DIN))[lane];
        __syncwarp();                         // WAR vs previous iteration's reads
        ((float2*)u_buf[w][0])[lane] = ra;
        ((float2*)u_buf[w][1])[lane] = rb;
        __syncwarp();
        const float4* uA = (const float4*)u_buf[w][0];
        const float4* uB = (const float4*)u_buf[w][1];

        // two independent logit dot-products, 2 accumulators each
        float lA0 = 0.f, lA1 = 0.f, lB0 = 0.f, lB1 = 0.f;
        #pragma unroll
        for (int k = 0; k < 16; k += 2) {
            float4 xA = uA[k], yA = uA[k + 1];
            float4 xB = uB[k], yB = uB[k + 1];
            lA0 = fmaf(xA.x, v4[k].x, lA0);     lA0 = fmaf(xA.y, v4[k].y, lA0);
            lA0 = fmaf(xA.z, v4[k].z, lA0);     lA0 = fmaf(xA.w, v4[k].w, lA0);
            lA1 = fmaf(yA.x, v4[k + 1].x, lA1); lA1 = fmaf(yA.y, v4[k + 1].y, lA1);
            lA1 = fmaf(yA.z, v4[k + 1].z, lA1); lA1 = fmaf(yA.w, v4[k + 1].w, lA1);
            lB0 = fmaf(xB.x, v4[k].x, lB0);     lB0 = fmaf(xB.y, v4[k].y, lB0);
            lB0 = fmaf(xB.z, v4[k].z, lB0);     lB0 = fmaf(xB.w, v4[k].w, lB0);
            lB1 = fmaf(yB.x, v4[k + 1].x, lB1); lB1 = fmaf(yB.y, v4[k + 1].y, lB1);
            lB1 = fmaf(yB.z, v4[k + 1].z, lB1); lB1 = fmaf(yB.w, v4[k + 1].w, lB1);
        }
        float eA = __expf(lA0 + lA1);
        float eB = __expf(lB0 + lB1);
        float sA = eA, sB = eB;
        #pragma unroll
        for (int off = 16; off; off >>= 1) {
            sA += __shfl_xor_sync(0xffffffffu, sA, off);
            sB += __shfl_xor_sync(0xffffffffu, sB, off);
        }
        float cA = __fdividef(eA, sA);
        float cB = __fdividef(eB, sB);

        // accumulate s[n,:] += cA*uA + cB*uB
        #pragma unroll
        for (int k = 0; k < 16; k++) {
            float4 xA = uA[k], xB = uB[k];
            s4[k].x = fmaf(cA, xA.x, fmaf(cB, xB.x, s4[k].x));
            s4[k].y = fmaf(cA, xA.y, fmaf(cB, xB.y, s4[k].y));
            s4[k].z = fmaf(cA, xA.z, fmaf(cB, xB.z, s4[k].z));
            s4[k].w = fmaf(cA, xA.w, fmaf(cB, xB.w, s4[k].w));
        }
    }

    // dump register s into padded smem (stride 65 -> conflict-free)
    #pragma unroll
    for (int k = 0; k < 16; k++) {
        s_blk[w][lane][4 * k + 0] = s4[k].x;
        s_blk[w][lane][4 * k + 1] = s4[k].y;
        s_blk[w][lane][4 * k + 2] = s4[k].z;
        s_blk[w][lane][4 * k + 3] = s4[k].w;
    }
    __syncthreads();

    // cross-warp reduce, deterministic, coalesced write of this block's partial
    float* outp = (float*)g_s_part[b][chunk];
    for (int e = threadIdx.x; e < NC * DIN; e += 128) {
        int n = e >> 6, i = e & 63;
        outp[e] = s_blk[0][n][i] + s_blk[1][n][i] + s_blk[2][n][i] + s_blk[3][n][i];
    }
}

// ---------------------------------------------------------------------------
extern "C" void kernel_launch(void* const* d_in, const int* in_sizes, int n_in,
                              void* d_out, int out_size) {
    const float* u = (const float*)d_in[0];   // [32, 2048, 64]
    const float* W = (const float*)d_in[1];   // [1, 64, 512]
    float* out = (float*)d_out;               // [32, 32, 16]

    // iteration 0: uniform c -> colsum path
    k1_colsum<<<dim3(K1_CHUNKS, BB), 256>>>(u);
    k2_update<<<dim3(NC, BB), 64>>>(W, out, 0);   // outputs0 + v0
    // iteration 1
    k3_route<<<dim3(K3_CHUNKS, BB), 128>>>(u);
    k2_update<<<dim3(NC, BB), 64>>>(W, out, 1);   // outputs1 + v1
    // iteration 2 (final)
    k3_route<<<dim3(K3_CHUNKS, BB), 128>>>(u);
    k2_update<<<dim3(NC, BB), 64>>>(W, out, 2);   // outputs2 -> d_out
}